// round 9
// baseline (speedup 1.0000x reference)
#include <cuda_runtime.h>
#include <math.h>

// Problem dims
#define SEQ   256
#define BATCH 64
#define IDIM  1024
#define HDIM  1024
#define PLEN  256
#define PDIM  1024

#define RBLOCKS  256
#define RTHREADS 256

typedef unsigned long long ull;

// -------- device scratch (no runtime allocation allowed) --------
__device__ float  g_gi[SEQ * BATCH * 3 * HDIM];        // input gates (f32)
__device__ float  g_h2[2 * BATCH * HDIM];              // double-buffered hidden state
__device__ float  g_scores[BATCH * SEQ * PLEN];        // [b][s][l]
__device__ unsigned g_bar;                             // grid barrier counter

// tf32 hi/lo split planes (x = hi, y = lo)
__device__ float2 g_in2[SEQ * BATCH * IDIM];           // incoming split
__device__ float2 g_Wih2[3 * HDIM * IDIM];             // W_ih split
__device__ float2 g_Wq2[PDIM * HDIM];                  // Wq split
__device__ float2 g_post2[PLEN * BATCH * PDIM];        // post split
__device__ float2 g_hs2[SEQ * BATCH * HDIM];           // h states split (dense)
__device__ float2 g_query2[SEQ * BATCH * PDIM];        // query split (phase C out)
__device__ float2 g_attn2[BATCH * SEQ * PLEN];         // attn split [b][s][l]

// =====================================================================
// helpers
// =====================================================================
__device__ __forceinline__ void cp_async16(void* smem_dst, const void* gmem_src)
{
    unsigned ds = (unsigned)__cvta_generic_to_shared(smem_dst);
    asm volatile("cp.async.cg.shared.global [%0], [%1], 16;\n" :: "r"(ds), "l"(gmem_src));
}

__device__ __forceinline__ unsigned f2tf(float x)
{
    unsigned r; asm("cvt.rna.tf32.f32 %0, %1;" : "=r"(r) : "f"(x)); return r;
}

__device__ __forceinline__ void mma8(float* c,
                                     unsigned a0, unsigned a1, unsigned a2, unsigned a3,
                                     unsigned b0, unsigned b1)
{
    asm volatile("mma.sync.aligned.m16n8k8.row.col.f32.tf32.tf32.f32 "
                 "{%0,%1,%2,%3},{%4,%5,%6,%7},{%8,%9},{%0,%1,%2,%3};"
                 : "+f"(c[0]), "+f"(c[1]), "+f"(c[2]), "+f"(c[3])
                 : "r"(a0), "r"(a1), "r"(a2), "r"(a3), "r"(b0), "r"(b1));
}

__device__ __forceinline__ ull fma2(ull a, ull b, ull c)
{
    ull d; asm("fma.rn.f32x2 %0, %1, %2, %3;" : "=l"(d) : "l"(a), "l"(b), "l"(c)); return d;
}

__device__ __forceinline__ ull add2(ull a, ull b)
{
    ull d; asm("add.rn.f32x2 %0, %1, %2;" : "=l"(d) : "l"(a), "l"(b)); return d;
}

__device__ __forceinline__ ull pack2(float x, float y)
{
    ull d; asm("mov.b64 %0, {%1, %2};" : "=l"(d) : "f"(x), "f"(y)); return d;
}

__device__ __forceinline__ float2 unpack2(ull v)
{
    float2 f; asm("mov.b64 {%0, %1}, %2;" : "=f"(f.x), "=f"(f.y) : "l"(v)); return f;
}

__device__ __forceinline__ float2 split_tf32(float x)
{
    float hi = __uint_as_float(f2tf(x));
    float lo = __uint_as_float(f2tf(x - hi));
    return make_float2(hi, lo);
}

// =====================================================================
// Elementwise tf32 split pre-pass: dst[i] = (hi, lo) of src[row*stride+col]
// =====================================================================
__global__ void split_kernel(const float* __restrict__ src, float2* __restrict__ dst,
                             long long n, int width, long long srcStride)
{
    long long stride = (long long)gridDim.x * blockDim.x;
    for (long long i = (long long)blockIdx.x * blockDim.x + threadIdx.x; i < n; i += stride) {
        long long r = i / width;
        int c = (int)(i - r * width);
        dst[i] = split_tf32(src[r * srcStride + c]);
    }
}

extern __shared__ float rsm[];

// =====================================================================
// Tensor-core tf32 (3xTF32) GEMM on pre-split operands, C = A * W^T (+bias)
//   A2 [M,K] float2 (hi,lo), rows stride lda; W2 [N,K] float2 rows stride ldw.
//   128x128x16 tiles, 8 warps (4M x 2N). 2-stage cp.async. smem stride 20
//   float2 per row -> conflict-free 8B fragment loads.
//   Output: f32 C (if C != null) else split float2 C2.
// =====================================================================
__global__ void __launch_bounds__(256)
tgemm_nt2(int M, int N, int K,
          const float2* __restrict__ A, long long lda, long long bsA,
          const float2* __restrict__ W, long long ldw, long long bsW,
          float* __restrict__ C, long long ldc, long long bsC,
          float2* __restrict__ C2, long long ldc2,
          const float* __restrict__ bias)
{
    float2* sA = (float2*)rsm;           // [2][128*20]
    float2* sB = sA + 2 * 2560;          // [2][128*20]

    const int tid = threadIdx.x;
    const int n0 = blockIdx.x * 128;
    const int m0 = blockIdx.y * 128;
    A += (long long)blockIdx.z * bsA;
    W += (long long)blockIdx.z * bsW;
    if (C) C += (long long)blockIdx.z * bsC;

    const int w    = tid >> 5;
    const int lane = tid & 31;
    const int lq   = lane >> 2;
    const int lr   = lane & 3;
    const int wm   = (w & 3) * 32;
    const int wn   = (w >> 2) * 64;

    float acc[2][8][4];
#pragma unroll
    for (int mt = 0; mt < 2; mt++)
#pragma unroll
        for (int nt = 0; nt < 8; nt++)
#pragma unroll
            for (int i = 0; i < 4; i++) acc[mt][nt][i] = 0.0f;

    const int nkt = K >> 4;

    auto load_stage = [&](int st, int kt) {
#pragma unroll
        for (int i = 0; i < 4; i++) {
            int idx = i * 256 + tid;          // 0..1023
            int row = idx >> 3, seg = idx & 7;
            cp_async16(&sA[st * 2560 + row * 20 + seg * 2],
                       A + (long long)(m0 + row) * lda + kt * 16 + seg * 2);
        }
#pragma unroll
        for (int i = 0; i < 4; i++) {
            int idx = i * 256 + tid;
            int row = idx >> 3, seg = idx & 7;
            cp_async16(&sB[st * 2560 + row * 20 + seg * 2],
                       W + (long long)(n0 + row) * ldw + kt * 16 + seg * 2);
        }
        asm volatile("cp.async.commit_group;\n");
    };

    load_stage(0, 0);

    for (int kt = 0; kt < nkt; kt++) {
        int cur = kt & 1;
        if (kt + 1 < nkt) {
            load_stage(cur ^ 1, kt + 1);
            asm volatile("cp.async.wait_group 1;\n");
        } else {
            asm volatile("cp.async.wait_group 0;\n");
        }
        __syncthreads();

        const float2* pA = sA + cur * 2560;
        const float2* pB = sB + cur * 2560;

#pragma unroll
        for (int kl = 0; kl < 16; kl += 8) {
            unsigned ah[2][4], al[2][4];
#pragma unroll
            for (int mt = 0; mt < 2; mt++) {
                int rb = wm + mt * 16 + lq;
                float2 a0 = pA[rb * 20 + kl + lr];
                float2 a1 = pA[(rb + 8) * 20 + kl + lr];
                float2 a2 = pA[rb * 20 + kl + 4 + lr];
                float2 a3 = pA[(rb + 8) * 20 + kl + 4 + lr];
                ah[mt][0] = __float_as_uint(a0.x); al[mt][0] = __float_as_uint(a0.y);
                ah[mt][1] = __float_as_uint(a1.x); al[mt][1] = __float_as_uint(a1.y);
                ah[mt][2] = __float_as_uint(a2.x); al[mt][2] = __float_as_uint(a2.y);
                ah[mt][3] = __float_as_uint(a3.x); al[mt][3] = __float_as_uint(a3.y);
            }
#pragma unroll
            for (int nt = 0; nt < 8; nt++) {
                int nr = wn + nt * 8 + lq;
                float2 b0 = pB[nr * 20 + kl + lr];
                float2 b1 = pB[nr * 20 + kl + 4 + lr];
                unsigned bh0 = __float_as_uint(b0.x), bl0 = __float_as_uint(b0.y);
                unsigned bh1 = __float_as_uint(b1.x), bl1 = __float_as_uint(b1.y);
#pragma unroll
                for (int mt = 0; mt < 2; mt++) {
                    mma8(acc[mt][nt], al[mt][0], al[mt][1], al[mt][2], al[mt][3], bh0, bh1);
                    mma8(acc[mt][nt], ah[mt][0], ah[mt][1], ah[mt][2], ah[mt][3], bl0, bl1);
                    mma8(acc[mt][nt], ah[mt][0], ah[mt][1], ah[mt][2], ah[mt][3], bh0, bh1);
                }
            }
        }
        __syncthreads();
    }

#pragma unroll
    for (int mt = 0; mt < 2; mt++) {
#pragma unroll
        for (int nt = 0; nt < 8; nt++) {
            int row = m0 + wm + mt * 16 + lq;
            int col = n0 + wn + nt * 8 + lr * 2;
            float bc0 = bias ? bias[col]     : 0.0f;
            float bc1 = bias ? bias[col + 1] : 0.0f;
            float c00 = acc[mt][nt][0] + bc0, c01 = acc[mt][nt][1] + bc1;
            float c10 = acc[mt][nt][2] + bc0, c11 = acc[mt][nt][3] + bc1;
            if (C) {
                *(float2*)&C[(long long)row * ldc + col]       = make_float2(c00, c01);
                *(float2*)&C[(long long)(row + 8) * ldc + col] = make_float2(c10, c11);
            } else {
                float2 s00 = split_tf32(c00), s01 = split_tf32(c01);
                float2 s10 = split_tf32(c10), s11 = split_tf32(c11);
                *(float4*)&C2[(long long)row * ldc2 + col] =
                    make_float4(s00.x, s00.y, s01.x, s01.y);
                *(float4*)&C2[(long long)(row + 8) * ldc2 + col] =
                    make_float4(s10.x, s10.y, s11.x, s11.y);
            }
        }
    }
}

// =====================================================================
// Tensor-core tf32 (3xTF32) GEMM on pre-split operands, C = A * B
//   A2 [M,K] float2 rows stride lda; B2 [K,N] float2 rows stride ldb.
// =====================================================================
__global__ void __launch_bounds__(256)
tgemm_nn2(int M, int N, int K,
          const float2* __restrict__ A, long long lda, long long bsA,
          const float2* __restrict__ B, long long ldb, long long bsB,
          float* __restrict__ C, long long ldc, long long bsC)
{
    float2* sA = (float2*)rsm;           // [2][128*20]
    float2* sB = sA + 2 * 2560;          // [2][16*132]

    const int tid = threadIdx.x;
    const int n0 = blockIdx.x * 128;
    const int m0 = blockIdx.y * 128;
    A += (long long)blockIdx.z * bsA;
    B += (long long)blockIdx.z * bsB;
    C += (long long)blockIdx.z * bsC;

    const int w    = tid >> 5;
    const int lane = tid & 31;
    const int lq   = lane >> 2;
    const int lr   = lane & 3;
    const int wm   = (w & 3) * 32;
    const int wn   = (w >> 2) * 64;

    float acc[2][8][4];
#pragma unroll
    for (int mt = 0; mt < 2; mt++)
#pragma unroll
        for (int nt = 0; nt < 8; nt++)
#pragma unroll
            for (int i = 0; i < 4; i++) acc[mt][nt][i] = 0.0f;

    const int nkt = K >> 4;

    auto load_stage = [&](int st, int kt) {
#pragma unroll
        for (int i = 0; i < 4; i++) {
            int idx = i * 256 + tid;
            int row = idx >> 3, seg = idx & 7;
            cp_async16(&sA[st * 2560 + row * 20 + seg * 2],
                       A + (long long)(m0 + row) * lda + kt * 16 + seg * 2);
        }
#pragma unroll
        for (int i = 0; i < 4; i++) {
            int idx = i * 256 + tid;
            int kr = idx >> 6, seg = idx & 63;
            cp_async16(&sB[st * 2112 + kr * 132 + seg * 2],
                       B + (long long)(kt * 16 + kr) * ldb + n0 + seg * 2);
        }
        asm volatile("cp.async.commit_group;\n");
    };

    load_stage(0, 0);

    for (int kt = 0; kt < nkt; kt++) {
        int cur = kt & 1;
        if (kt + 1 < nkt) {
            load_stage(cur ^ 1, kt + 1);
            asm volatile("cp.async.wait_group 1;\n");
        } else {
            asm volatile("cp.async.wait_group 0;\n");
        }
        __syncthreads();

        const float2* pA = sA + cur * 2560;
        const float2* pB = sB + cur * 2112;

#pragma unroll
        for (int kl = 0; kl < 16; kl += 8) {
            unsigned ah[2][4], al[2][4];
#pragma unroll
            for (int mt = 0; mt < 2; mt++) {
                int rb = wm + mt * 16 + lq;
                float2 a0 = pA[rb * 20 + kl + lr];
                float2 a1 = pA[(rb + 8) * 20 + kl + lr];
                float2 a2 = pA[rb * 20 + kl + 4 + lr];
                float2 a3 = pA[(rb + 8) * 20 + kl + 4 + lr];
                ah[mt][0] = __float_as_uint(a0.x); al[mt][0] = __float_as_uint(a0.y);
                ah[mt][1] = __float_as_uint(a1.x); al[mt][1] = __float_as_uint(a1.y);
                ah[mt][2] = __float_as_uint(a2.x); al[mt][2] = __float_as_uint(a2.y);
                ah[mt][3] = __float_as_uint(a3.x); al[mt][3] = __float_as_uint(a3.y);
            }
#pragma unroll
            for (int nt = 0; nt < 8; nt++) {
                int nc = wn + nt * 8 + lq;
                float2 b0 = pB[(kl + lr) * 132 + nc];
                float2 b1 = pB[(kl + 4 + lr) * 132 + nc];
                unsigned bh0 = __float_as_uint(b0.x), bl0 = __float_as_uint(b0.y);
                unsigned bh1 = __float_as_uint(b1.x), bl1 = __float_as_uint(b1.y);
#pragma unroll
                for (int mt = 0; mt < 2; mt++) {
                    mma8(acc[mt][nt], al[mt][0], al[mt][1], al[mt][2], al[mt][3], bh0, bh1);
                    mma8(acc[mt][nt], ah[mt][0], ah[mt][1], ah[mt][2], ah[mt][3], bl0, bl1);
                    mma8(acc[mt][nt], ah[mt][0], ah[mt][1], ah[mt][2], ah[mt][3], bh0, bh1);
                }
            }
        }
        __syncthreads();
    }

#pragma unroll
    for (int mt = 0; mt < 2; mt++) {
#pragma unroll
        for (int nt = 0; nt < 8; nt++) {
            int row = m0 + wm + mt * 16 + lq;
            int col = n0 + wn + nt * 8 + lr * 2;
            *(float2*)&C[(long long)row * ldc + col] =
                make_float2(acc[mt][nt][0], acc[mt][nt][1]);
            *(float2*)&C[(long long)(row + 8) * ldc + col] =
                make_float2(acc[mt][nt][2], acc[mt][nt][3]);
        }
    }
}

// =====================================================================
// Persistent GRU recurrence — packed f32x2 FFMA version.
//   256 blocks x 256 threads, 2 blocks/SM. Block owns 4 hidden cols j
//   (12 W_hh rows packed into 6 column-pair float2 rows, stationary in
//   smem). h broadcast per step via cp.async.cg double-buffered chunks.
//   acc2[i][ccp] packs (col 2ccp, col 2ccp+1) partial sums -> one
//   fma.rn.f32x2 per 2 MACs. 16-lane butterfly reduce with add.rn.f32x2.
// =====================================================================
__global__ void __launch_bounds__(RTHREADS, 2)
gru_persistent(const float* __restrict__ gi,
               const float* __restrict__ W_hh,
               const float* __restrict__ b_hh,
               const float* __restrict__ h_init,
               const int* __restrict__ length,
               float* __restrict__ h2,          // [2][B*H]
               float* __restrict__ out_hs,      // [S][B][2H]
               float* __restrict__ out_hlast,   // [B][H]
               unsigned* __restrict__ bar)
{
    const int tid = threadIdx.x;
    const int bg  = tid >> 4;        // 0..15 -> batches [4bg, 4bg+4)
    const int ks  = tid & 15;        // k-slice / gate-lane id
    const int j0  = blockIdx.x * 4;
    const int b   = bg * 4 + (ks >> 2);
    const int j   = j0 + (ks & 3);

    float2* Ws2 = (float2*)rsm;      // 6 x 1024 float2 (column pairs)
    float* hb0 = rsm + 12 * 1024;    // 64 x 64 f32 chunk
    float* hb1 = hb0 + 64 * 64;

    // ---- build stationary packed W slice: Ws2[ccp*1024+k] = (W_cc0[k], W_cc1[k])
    // cc = 3*jj + g  -> W_hh row g*1024 + j0 + jj
    for (int v = tid; v < 6 * 1024; v += RTHREADS) {
        int ccp = v >> 10, k = v & 1023;
        int cc0 = ccp * 2, cc1 = cc0 + 1;
        int row0 = (cc0 % 3) * 1024 + j0 + cc0 / 3;
        int row1 = (cc1 % 3) * 1024 + j0 + cc1 / 3;
        Ws2[v] = make_float2(W_hh[row0 * 1024 + k], W_hh[row1 * 1024 + k]);
    }

    const float bh_r = b_hh[j];
    const float bh_z = b_hh[1024 + j];
    const float bh_n = b_hh[2048 + j];
    const int   len_b = length[b];

    // ---- init h buffer 0
    {
        int v = blockIdx.x * RTHREADS + tid;
        h2[v] = h_init[v & (HDIM - 1)];
    }

    unsigned phase = 1;
    {
        __threadfence(); __syncthreads();
        if (tid == 0) {
            atomicAdd(bar, 1u);
            while (*((volatile unsigned*)bar) < phase * RBLOCKS) { __nanosleep(32); }
        }
        __syncthreads();
    }

    const ull* Wsu = (const ull*)Ws2;

    for (int s = 0; s < SEQ; s++) {
        const float* hcur = h2 + (s & 1) * (BATCH * HDIM);
        float*       hnxt = h2 + ((s + 1) & 1) * (BATCH * HDIM);
        const float4* hc4 = (const float4*)hcur;

        const float* gis = gi + (long long)s * (BATCH * 3 * HDIM) + b * 3 * HDIM;
        float gi_r  = __ldg(&gis[j]);
        float gi_z  = __ldg(&gis[1024 + j]);
        float gi_n  = __ldg(&gis[2048 + j]);
        float h_old = __ldcg(&hcur[b * 1024 + j]);

        ull acc2[4][6];
#pragma unroll
        for (int i = 0; i < 4; i++)
#pragma unroll
            for (int p = 0; p < 6; p++) acc2[i][p] = 0ull;

        // stage chunk 0
        {
            float4* dst = (float4*)hb0;
#pragma unroll
            for (int i = 0; i < 4; i++) {
                int idx = i * 256 + tid;
                int bb = idx >> 4, kq = idx & 15;
                cp_async16(&dst[bb * 16 + kq], &hc4[bb * 256 + kq]);
            }
            asm volatile("cp.async.commit_group;\n");
        }

        for (int c = 0; c < 16; c++) {
            const float* cur = (c & 1) ? hb1 : hb0;
            float*       nxt = (c & 1) ? hb0 : hb1;
            if (c + 1 < 16) {
                float4* dst = (float4*)nxt;
#pragma unroll
                for (int i = 0; i < 4; i++) {
                    int idx = i * 256 + tid;
                    int bb = idx >> 4, kq = idx & 15;
                    cp_async16(&dst[bb * 16 + kq], &hc4[bb * 256 + (c + 1) * 16 + kq]);
                }
                asm volatile("cp.async.commit_group;\n");
                asm volatile("cp.async.wait_group 1;\n");
            } else {
                asm volatile("cp.async.wait_group 0;\n");
            }
            __syncthreads();

            float hav[4][4];
#pragma unroll
            for (int i = 0; i < 4; i++)
                *(float4*)&hav[i][0] = *(const float4*)&cur[(bg * 4 + i) * 64 + ks * 4];

            const int kbase = c * 64 + ks * 4;
#pragma unroll
            for (int kk = 0; kk < 4; kk++) {
                ull hp0 = pack2(hav[0][kk], hav[0][kk]);
                ull hp1 = pack2(hav[1][kk], hav[1][kk]);
                ull hp2 = pack2(hav[2][kk], hav[2][kk]);
                ull hp3 = pack2(hav[3][kk], hav[3][kk]);
#pragma unroll
                for (int p = 0; p < 6; p++) {
                    ull wv = Wsu[p * 1024 + kbase + kk];
                    acc2[0][p] = fma2(hp0, wv, acc2[0][p]);
                    acc2[1][p] = fma2(hp1, wv, acc2[1][p]);
                    acc2[2][p] = fma2(hp2, wv, acc2[2][p]);
                    acc2[3][p] = fma2(hp3, wv, acc2[3][p]);
                }
            }
            __syncthreads();
        }

        // butterfly reduce over 16 k-slices (stays within 16-lane halves)
#pragma unroll
        for (int off = 8; off > 0; off >>= 1)
#pragma unroll
            for (int i = 0; i < 4; i++)
#pragma unroll
                for (int p = 0; p < 6; p++) {
                    ull o = __shfl_xor_sync(0xffffffffu, acc2[i][p], off);
                    acc2[i][p] = add2(acc2[i][p], o);
                }

        // fused gates: lane handles (b, j)
        {
            int bi = ks >> 2, jj = ks & 3;
            int cc_r = jj * 3 + 0, cc_z = jj * 3 + 1, cc_n = jj * 3 + 2;
            float2 fr = unpack2(acc2[bi][cc_r >> 1]);
            float2 fz = unpack2(acc2[bi][cc_z >> 1]);
            float2 fn = unpack2(acc2[bi][cc_n >> 1]);
            float ghr = ((cc_r & 1) ? fr.y : fr.x) + bh_r;
            float ghz = ((cc_z & 1) ? fz.y : fz.x) + bh_z;
            float ghn = ((cc_n & 1) ? fn.y : fn.x) + bh_n;
            float r = 1.0f / (1.0f + expf(-(gi_r + ghr)));
            float z = 1.0f / (1.0f + expf(-(gi_z + ghz)));
            float n = tanhf(gi_n + r * ghn);
            float keep = (s < len_b) ? 1.0f : 0.0f;
            float hnew = (n + z * (h_old - n)) * keep;

            hnxt[b * 1024 + j] = hnew;
            out_hs[(long long)s * (BATCH * 2 * HDIM) + b * (2 * HDIM) + j] = hnew;
            if (s == SEQ - 1) out_hlast[b * 1024 + j] = hnew;
        }

        phase++;
        __threadfence(); __syncthreads();
        if (tid == 0) {
            atomicAdd(bar, 1u);
            while (*((volatile unsigned*)bar) < phase * RBLOCKS) { __nanosleep(32); }
        }
        __syncthreads();
    }
}

// =====================================================================
// Softmax: writes f32 out_attn and pre-split attn for the D3 GEMM
// =====================================================================
__global__ void attn_softmax_kernel(const float* __restrict__ scores,   // [b][s][l]
                                    const int* __restrict__ post_length,
                                    float2* __restrict__ attn2,         // [b][s][l] split
                                    float* __restrict__ out_attn)       // [s][l][b]
{
    int s = blockIdx.x;
    int b = blockIdx.y;
    int l = threadIdx.x;

    float sc = scores[((long long)b * SEQ + s) * PLEN + l];
    if (l >= post_length[b]) sc = -1000000000.0f;

    __shared__ float red[PLEN];
    red[l] = sc;
    __syncthreads();
#pragma unroll
    for (int o = PLEN / 2; o > 0; o >>= 1) {
        if (l < o) red[l] = fmaxf(red[l], red[l + o]);
        __syncthreads();
    }
    float mx = red[0];
    __syncthreads();

    float e = expf(sc - mx);
    red[l] = e;
    __syncthreads();
#pragma unroll
    for (int o = PLEN / 2; o > 0; o >>= 1) {
        if (l < o) red[l] += red[l + o];
        __syncthreads();
    }
    float a = e / red[0];

    attn2[((long long)b * SEQ + s) * PLEN + l] = split_tf32(a);
    out_attn[(long long)s * (PLEN * BATCH) + l * BATCH + b] = a;
}

// =====================================================================
// launch
// =====================================================================
extern "C" void kernel_launch(void* const* d_in, const int* in_sizes, int n_in,
                              void* d_out, int out_size)
{
    (void)in_sizes; (void)n_in; (void)out_size;

    const float* incoming = (const float*)d_in[0];
    const float* post     = (const float*)d_in[1];
    const float* h_init   = (const float*)d_in[2];
    const float* W_ih     = (const float*)d_in[3];
    const float* W_hh     = (const float*)d_in[4];
    const float* b_ih     = (const float*)d_in[5];
    const float* b_hh     = (const float*)d_in[6];
    const float* Wq       = (const float*)d_in[7];
    const float* bq       = (const float*)d_in[8];
    const int*   length      = (const int*)d_in[9];
    const int*   post_length = (const int*)d_in[10];

    float* out       = (float*)d_out;
    float* out_hlast = out;                                   // [B, H]
    float* out_hs    = out + BATCH * HDIM;                    // [S, B, 2H]
    float* out_attn  = out_hs + (long long)SEQ * BATCH * 2 * HDIM;  // [S, PL, B]

    float *gi, *h2, *scores;
    float2 *in2, *Wih2, *Wq2, *post2, *hs2, *query2, *attn2;
    unsigned* bar;
    cudaGetSymbolAddress((void**)&gi,     g_gi);
    cudaGetSymbolAddress((void**)&h2,     g_h2);
    cudaGetSymbolAddress((void**)&scores, g_scores);
    cudaGetSymbolAddress((void**)&bar,    g_bar);
    cudaGetSymbolAddress((void**)&in2,    g_in2);
    cudaGetSymbolAddress((void**)&Wih2,   g_Wih2);
    cudaGetSymbolAddress((void**)&Wq2,    g_Wq2);
    cudaGetSymbolAddress((void**)&post2,  g_post2);
    cudaGetSymbolAddress((void**)&hs2,    g_hs2);
    cudaGetSymbolAddress((void**)&query2, g_query2);
    cudaGetSymbolAddress((void**)&attn2,  g_attn2);

    cudaFuncSetAttribute(gru_persistent,
                         cudaFuncAttributeMaxDynamicSharedMemorySize, 81920);
    cudaFuncSetAttribute(tgemm_nt2,
                         cudaFuncAttributeMaxDynamicSharedMemorySize, 81920);
    cudaFuncSetAttribute(tgemm_nn2,
                         cudaFuncAttributeMaxDynamicSharedMemorySize, 74752);

    const int MALL = SEQ * BATCH;   // 16384

    // ---- tf32 split pre-passes (dense inputs)
    split_kernel<<<2048, 256>>>(incoming, in2, (long long)MALL * IDIM, IDIM, IDIM);
    split_kernel<<<2048, 256>>>(W_ih, Wih2, (long long)3 * HDIM * IDIM, IDIM, IDIM);
    split_kernel<<<512,  256>>>(Wq, Wq2, (long long)PDIM * HDIM, HDIM, HDIM);
    split_kernel<<<2048, 256>>>(post, post2, (long long)PLEN * BATCH * PDIM, PDIM, PDIM);

    // Phase A: gi = incoming @ W_ih^T + b_ih  [16384, 3072] k=1024 -> f32
    tgemm_nt2<<<dim3(3 * HDIM / 128, MALL / 128), 256, 81920>>>(
        MALL, 3 * HDIM, IDIM,
        in2, IDIM, 0,
        Wih2, IDIM, 0,
        gi, 3 * HDIM, 0,
        (float2*)nullptr, 0,
        b_ih);

    // Phase B: persistent fused GRU recurrence (f32x2 packed FFMA)
    cudaMemsetAsync(bar, 0, sizeof(unsigned));
    gru_persistent<<<RBLOCKS, RTHREADS, 81920>>>(
        gi, W_hh, b_hh, h_init, length, h2, out_hs, out_hlast, bar);

    // split hidden states (strided read from out_hs first halves)
    split_kernel<<<2048, 256>>>(out_hs, hs2, (long long)MALL * HDIM, HDIM, 2 * HDIM);

    // Phase C: query = h_all @ Wq^T + bq -> split float2 output
    tgemm_nt2<<<dim3(PDIM / 128, MALL / 128), 256, 81920>>>(
        MALL, PDIM, HDIM,
        hs2, HDIM, 0,
        Wq2, HDIM, 0,
        (float*)nullptr, 0, 0,
        query2, PDIM,
        bq);

    // Phase D1: scores_b = Q_b @ post_b^T (batched over b) -> f32
    tgemm_nt2<<<dim3(PLEN / 128, SEQ / 128, BATCH), 256, 81920>>>(
        SEQ, PLEN, PDIM,
        query2, (long long)BATCH * PDIM, PDIM,
        post2, (long long)BATCH * PDIM, PDIM,
        scores, PLEN, (long long)SEQ * PLEN,
        (float2*)nullptr, 0,
        (const float*)nullptr);

    // Phase D2: masked softmax over l (writes split attn + f32 out_attn)
    attn_softmax_kernel<<<dim3(SEQ, BATCH), PLEN>>>(scores, post_length, attn2, out_attn);

    // Phase D3: context_b = attn_b @ post_b -> hs[:, b, H:2H]
    tgemm_nn2<<<dim3(PDIM / 128, SEQ / 128, BATCH), 256, 74752>>>(
        SEQ, PDIM, PLEN,
        attn2, PLEN, (long long)SEQ * PLEN,
        post2, (long long)BATCH * PDIM, PDIM,
        out_hs + HDIM, (long long)BATCH * 2 * HDIM, 2 * HDIM);
}